// round 6
// baseline (speedup 1.0000x reference)
#include <cuda_runtime.h>
#include <cstdint>

#define LOG2E 1.4426950408889634f
#define NPTS 4096

#define FMA2(a, b, c) \
    asm("fma.rn.f32x2 %0, %1, %2, %0;" : "+l"(a) : "l"(b), "l"(c))

// Fused RBF covariance: cov[i,j] = exp2( sum_d U[i,d]*V[j,d] + c_i + d_j )
// Tile 128(i) x 64(j) per CTA, 256 threads, 4x8 outputs/thread,
// 64 regs/thread -> 4 CTAs/SM (32 warps) for latency hiding.
__global__ void __launch_bounds__(256, 4) rbf_fused(
    const float* __restrict__ x,         // [4096,16]
    const float* __restrict__ xx,        // [4096,16]
    const float* __restrict__ scale_ff,  // [16]
    const float* __restrict__ var_ff,    // scalar
    float* __restrict__ out)             // [4096,4096]
{
    __shared__ __align__(16) float Ud[16][256];  // dup pairs: Ud[d][2i]=Ud[d][2i+1]=u_i
    __shared__ __align__(16) float Vs[16][64];
    __shared__ float cs[128];
    __shared__ float dsm[64];
    __shared__ float s_inv[16];
    __shared__ float s_l2var;

    const int tid = threadIdx.x;
    const int tx = tid & 7;        // 8 j-groups (8 j each)
    const int ty = tid >> 3;       // 32 i-groups (4 i each)
    const int bi0 = blockIdx.y * 128;
    const int bj0 = blockIdx.x * 64;

    // ---- phase 0: softplus params once into smem ----
    if (tid < 16) {
        float s = log1pf(__expf(scale_ff[tid]));
        s_inv[tid] = 1.0f / s;
    } else if (tid == 16) {
        s_l2var = log2f(log1pf(__expf(var_ff[0])));
    }
    __syncthreads();

    // ---- phase 1: build U/V tiles + row/col norm terms ----
    if (tid < 128) {
        const float4* row = (const float4*)(x + (size_t)(bi0 + tid) * 16);
        float4 a = row[0], b = row[1], c4 = row[2], e = row[3];
        float v[16] = {a.x, a.y, a.z, a.w, b.x, b.y, b.z, b.w,
                       c4.x, c4.y, c4.z, c4.w, e.x, e.y, e.z, e.w};
        float s2 = 0.0f;
#pragma unroll
        for (int d = 0; d < 16; d++) {
            float u = v[d] * s_inv[d];
            ((float2*)&Ud[d][0])[tid] = make_float2(u, u);
            s2 = fmaf(u, u, s2);
        }
        cs[tid] = -0.5f * LOG2E * s2;
    } else if (tid < 192) {
        const int j = tid - 128;   // 0..63
        const float4* row = (const float4*)(xx + (size_t)(bj0 + j) * 16);
        float4 a = row[0], b = row[1], c4 = row[2], e = row[3];
        float v[16] = {a.x, a.y, a.z, a.w, b.x, b.y, b.z, b.w,
                       c4.x, c4.y, c4.z, c4.w, e.x, e.y, e.z, e.w};
        float s2 = 0.0f;
#pragma unroll
        for (int d = 0; d < 16; d++) {
            float u = v[d] * s_inv[d];
            Vs[d][j] = LOG2E * u;
            s2 = fmaf(u, u, s2);
        }
        dsm[j] = -0.5f * LOG2E * s2 + s_l2var;
    }
    __syncthreads();

    // ---- accumulator init: acc = c_i + d_j ----
    unsigned long long acc[4][4];
#pragma unroll
    for (int r = 0; r < 4; r++) {
        float ci = cs[ty * 4 + r];
#pragma unroll
        for (int jp = 0; jp < 4; jp++) {
            float lo = ci + dsm[tx * 8 + 2 * jp];
            float hi = ci + dsm[tx * 8 + 2 * jp + 1];
            asm("mov.b64 %0, {%1, %2};" : "=l"(acc[r][jp]) : "f"(lo), "f"(hi));
        }
    }

    // ---- mainloop: D=16 unrolled; 4 LDS.128 + 16 fma.rn.f32x2 per d ----
#pragma unroll
    for (int d = 0; d < 16; d++) {
        const ulonglong2* up = (const ulonglong2*)&Ud[d][0];  // 16B units
        const ulonglong2* vp = (const ulonglong2*)&Vs[d][0];
        ulonglong2 u0 = up[2 * ty];       // dup(i0), dup(i1)
        ulonglong2 u1 = up[2 * ty + 1];   // dup(i2), dup(i3)
        ulonglong2 va = vp[2 * tx];       // (j0,j1),(j2,j3)
        ulonglong2 vb = vp[2 * tx + 1];   // (j4,j5),(j6,j7)

        FMA2(acc[0][0], u0.x, va.x); FMA2(acc[0][1], u0.x, va.y);
        FMA2(acc[0][2], u0.x, vb.x); FMA2(acc[0][3], u0.x, vb.y);
        FMA2(acc[1][0], u0.y, va.x); FMA2(acc[1][1], u0.y, va.y);
        FMA2(acc[1][2], u0.y, vb.x); FMA2(acc[1][3], u0.y, vb.y);
        FMA2(acc[2][0], u1.x, va.x); FMA2(acc[2][1], u1.x, va.y);
        FMA2(acc[2][2], u1.x, vb.x); FMA2(acc[2][3], u1.x, vb.y);
        FMA2(acc[3][0], u1.y, va.x); FMA2(acc[3][1], u1.y, va.y);
        FMA2(acc[3][2], u1.y, vb.x); FMA2(acc[3][3], u1.y, vb.y);
    }

    // ---- epilogue: MUFU.EX2 + float4 stores (no temp arrays) ----
#pragma unroll
    for (int r = 0; r < 4; r++) {
        const size_t rowoff = (size_t)(bi0 + ty * 4 + r) * NPTS + bj0 + tx * 8;
        float f0, f1, f2, f3, f4, f5, f6, f7;
        asm("mov.b64 {%0, %1}, %2;" : "=f"(f0), "=f"(f1) : "l"(acc[r][0]));
        asm("mov.b64 {%0, %1}, %2;" : "=f"(f2), "=f"(f3) : "l"(acc[r][1]));
        asm("mov.b64 {%0, %1}, %2;" : "=f"(f4), "=f"(f5) : "l"(acc[r][2]));
        asm("mov.b64 {%0, %1}, %2;" : "=f"(f6), "=f"(f7) : "l"(acc[r][3]));
        asm("ex2.approx.ftz.f32 %0, %0;" : "+f"(f0));
        asm("ex2.approx.ftz.f32 %0, %0;" : "+f"(f1));
        asm("ex2.approx.ftz.f32 %0, %0;" : "+f"(f2));
        asm("ex2.approx.ftz.f32 %0, %0;" : "+f"(f3));
        asm("ex2.approx.ftz.f32 %0, %0;" : "+f"(f4));
        asm("ex2.approx.ftz.f32 %0, %0;" : "+f"(f5));
        asm("ex2.approx.ftz.f32 %0, %0;" : "+f"(f6));
        asm("ex2.approx.ftz.f32 %0, %0;" : "+f"(f7));
        *(float4*)&out[rowoff]     = make_float4(f0, f1, f2, f3);
        *(float4*)&out[rowoff + 4] = make_float4(f4, f5, f6, f7);
    }
}

extern "C" void kernel_launch(void* const* d_in, const int* in_sizes, int n_in,
                              void* d_out, int out_size) {
    const float* x        = (const float*)d_in[0];
    const float* xx       = (const float*)d_in[1];
    const float* scale_ff = (const float*)d_in[2];
    const float* var_ff   = (const float*)d_in[3];
    float* out = (float*)d_out;

    dim3 grid(NPTS / 64, NPTS / 128);   // x: j-tiles, y: i-tiles
    rbf_fused<<<grid, 256>>>(x, xx, scale_ff, var_ff, out);
}

// round 7
// speedup vs baseline: 1.4727x; 1.4727x over previous
#include <cuda_runtime.h>
#include <cstdint>

#define LOG2E 1.4426950408889634f
#define NPTS 4096

#define FMA2(a, b, c) \
    asm("fma.rn.f32x2 %0, %1, %2, %0;" : "+l"(a) : "l"(b), "l"(c))

// Fused RBF covariance: cov[i,j] = exp2( sum_d U[i,d]*V[j,d] + c_i + d_j )
// 128x128 tile, 256 threads, 8x8 outputs/thread (R1 mainloop shape),
// preamble latency hidden: row LDGs issued first, softplus overlapped.
__global__ void __launch_bounds__(256, 2) rbf_fused(
    const float* __restrict__ x,         // [4096,16]
    const float* __restrict__ xx,        // [4096,16]
    const float* __restrict__ scale_ff,  // [16]
    const float* __restrict__ var_ff,    // scalar
    float* __restrict__ out)             // [4096,4096]
{
    __shared__ __align__(16) float Ud[16][256];  // dup pairs: Ud[d][2i]=Ud[d][2i+1]=u_i
    __shared__ __align__(16) float Vs[16][128];
    __shared__ float cs[128];
    __shared__ float dsm[128];
    __shared__ float s_inv[16];
    __shared__ float s_l2var;

    const int tid = threadIdx.x;
    const int tx = tid & 15;
    const int ty = tid >> 4;
    const int bi0 = blockIdx.y * 128;
    const int bj0 = blockIdx.x * 128;   // consecutive bids -> adjacent j-stripes

    // ---- phase 1a: one row per thread, LDG.128 x4 issued immediately ----
    const bool is_x = (tid < 128);
    const float4* rowp = is_x
        ? (const float4*)(x  + (size_t)(bi0 + tid) * 16)
        : (const float4*)(xx + (size_t)(bj0 + (tid - 128)) * 16);
    float4 ra = rowp[0], rb = rowp[1], rc = rowp[2], rd = rowp[3];

    // ---- phase 1b: softplus params in warp 0, overlapped with LDG latency ----
    if (tid < 16) {
        s_inv[tid] = 1.0f / log1pf(__expf(scale_ff[tid]));
    } else if (tid == 16) {
        s_l2var = log2f(log1pf(__expf(var_ff[0])));
    }
    __syncthreads();

    // ---- phase 1c: scale rows, build tiles + norm terms ----
    {
        float v[16] = {ra.x, ra.y, ra.z, ra.w, rb.x, rb.y, rb.z, rb.w,
                       rc.x, rc.y, rc.z, rc.w, rd.x, rd.y, rd.z, rd.w};
        float s2 = 0.0f;
        if (is_x) {
#pragma unroll
            for (int d = 0; d < 16; d++) {
                float u = v[d] * s_inv[d];
                ((float2*)&Ud[d][0])[tid] = make_float2(u, u);
                s2 = fmaf(u, u, s2);
            }
            cs[tid] = -0.5f * LOG2E * s2;
        } else {
            const int j = tid - 128;
#pragma unroll
            for (int d = 0; d < 16; d++) {
                float u = v[d] * s_inv[d];
                Vs[d][j] = LOG2E * u;
                s2 = fmaf(u, u, s2);
            }
            dsm[j] = -0.5f * LOG2E * s2 + s_l2var;
        }
    }
    __syncthreads();

    // ---- accumulator init: acc = c_i + d_j ----
    float cv[8], dv8[8];
#pragma unroll
    for (int r = 0; r < 4; r++) {
        cv[r]      = cs[ty * 4 + r];
        cv[4 + r]  = cs[64 + ty * 4 + r];
        dv8[r]     = dsm[tx * 4 + r];
        dv8[4 + r] = dsm[64 + tx * 4 + r];
    }
    unsigned long long acc[8][4];
#pragma unroll
    for (int ii = 0; ii < 8; ii++) {
#pragma unroll
        for (int jp = 0; jp < 4; jp++) {
            float lo = cv[ii] + dv8[2 * jp];
            float hi = cv[ii] + dv8[2 * jp + 1];
            asm("mov.b64 %0, {%1, %2};" : "=l"(acc[ii][jp]) : "f"(lo), "f"(hi));
        }
    }

    // ---- mainloop: D=16 unrolled; 6 LDS.128 + 32 fma.rn.f32x2 per d ----
#pragma unroll
    for (int d = 0; d < 16; d++) {
        const ulonglong2* up = (const ulonglong2*)&Ud[d][0];  // 16B units
        const ulonglong2* vp = (const ulonglong2*)&Vs[d][0];
        ulonglong2 u0 = up[2 * ty];          // dup(i0),dup(i1)
        ulonglong2 u1 = up[2 * ty + 1];      // dup(i2),dup(i3)
        ulonglong2 u2 = up[32 + 2 * ty];     // dup(i4),dup(i5)
        ulonglong2 u3 = up[33 + 2 * ty];     // dup(i6),dup(i7)
        ulonglong2 va = vp[tx];              // (j0,j1),(j2,j3)
        ulonglong2 vb = vp[16 + tx];         // (j4,j5),(j6,j7)

        FMA2(acc[0][0], u0.x, va.x); FMA2(acc[0][1], u0.x, va.y);
        FMA2(acc[0][2], u0.x, vb.x); FMA2(acc[0][3], u0.x, vb.y);
        FMA2(acc[1][0], u0.y, va.x); FMA2(acc[1][1], u0.y, va.y);
        FMA2(acc[1][2], u0.y, vb.x); FMA2(acc[1][3], u0.y, vb.y);
        FMA2(acc[2][0], u1.x, va.x); FMA2(acc[2][1], u1.x, va.y);
        FMA2(acc[2][2], u1.x, vb.x); FMA2(acc[2][3], u1.x, vb.y);
        FMA2(acc[3][0], u1.y, va.x); FMA2(acc[3][1], u1.y, va.y);
        FMA2(acc[3][2], u1.y, vb.x); FMA2(acc[3][3], u1.y, vb.y);
        FMA2(acc[4][0], u2.x, va.x); FMA2(acc[4][1], u2.x, va.y);
        FMA2(acc[4][2], u2.x, vb.x); FMA2(acc[4][3], u2.x, vb.y);
        FMA2(acc[5][0], u2.y, va.x); FMA2(acc[5][1], u2.y, va.y);
        FMA2(acc[5][2], u2.y, vb.x); FMA2(acc[5][3], u2.y, vb.y);
        FMA2(acc[6][0], u3.x, va.x); FMA2(acc[6][1], u3.x, va.y);
        FMA2(acc[6][2], u3.x, vb.x); FMA2(acc[6][3], u3.x, vb.y);
        FMA2(acc[7][0], u3.y, va.x); FMA2(acc[7][1], u3.y, va.y);
        FMA2(acc[7][2], u3.y, vb.x); FMA2(acc[7][3], u3.y, vb.y);
    }

    // ---- epilogue: MUFU.EX2 + float4 stores ----
#pragma unroll
    for (int ii = 0; ii < 8; ii++) {
        int ig = bi0 + ((ii < 4) ? (ty * 4 + ii) : (64 + ty * 4 + (ii - 4)));
        float f0, f1, f2, f3, f4, f5, f6, f7;
        asm("mov.b64 {%0, %1}, %2;" : "=f"(f0), "=f"(f1) : "l"(acc[ii][0]));
        asm("mov.b64 {%0, %1}, %2;" : "=f"(f2), "=f"(f3) : "l"(acc[ii][1]));
        asm("mov.b64 {%0, %1}, %2;" : "=f"(f4), "=f"(f5) : "l"(acc[ii][2]));
        asm("mov.b64 {%0, %1}, %2;" : "=f"(f6), "=f"(f7) : "l"(acc[ii][3]));
        asm("ex2.approx.ftz.f32 %0, %0;" : "+f"(f0));
        asm("ex2.approx.ftz.f32 %0, %0;" : "+f"(f1));
        asm("ex2.approx.ftz.f32 %0, %0;" : "+f"(f2));
        asm("ex2.approx.ftz.f32 %0, %0;" : "+f"(f3));
        asm("ex2.approx.ftz.f32 %0, %0;" : "+f"(f4));
        asm("ex2.approx.ftz.f32 %0, %0;" : "+f"(f5));
        asm("ex2.approx.ftz.f32 %0, %0;" : "+f"(f6));
        asm("ex2.approx.ftz.f32 %0, %0;" : "+f"(f7));
        *(float4*)&out[(size_t)ig * NPTS + bj0 + 4 * tx]      = make_float4(f0, f1, f2, f3);
        *(float4*)&out[(size_t)ig * NPTS + bj0 + 64 + 4 * tx] = make_float4(f4, f5, f6, f7);
    }
}

extern "C" void kernel_launch(void* const* d_in, const int* in_sizes, int n_in,
                              void* d_out, int out_size) {
    const float* x        = (const float*)d_in[0];
    const float* xx       = (const float*)d_in[1];
    const float* scale_ff = (const float*)d_in[2];
    const float* var_ff   = (const float*)d_in[3];
    float* out = (float*)d_out;

    dim3 grid(NPTS / 128, NPTS / 128);
    rbf_fused<<<grid, 256>>>(x, xx, scale_ff, var_ff, out);
}

// round 8
// speedup vs baseline: 1.5676x; 1.0645x over previous
#include <cuda_runtime.h>
#include <cstdint>

#define LOG2E 1.4426950408889634f
#define NPTS 4096

#define FMA2(a, b, c) \
    asm("fma.rn.f32x2 %0, %1, %2, %0;" : "+l"(a) : "l"(b), "l"(c))

// Fused RBF covariance: cov[i,j] = exp2( sum_d U[i,d]*V[j,d] + c_i + d_j )
// 128x128 tile, 256 threads. Tile processed as two j-halves sequentially:
// mainA -> epiA -> mainB -> epiB (no syncs between) so epilogue MUFU/STG of
// one phase overlaps FMA of the next across drifting warps, and 32-reg
// accumulators leave room for deep LDS pipelining at 2 CTAs/SM.
__global__ void __launch_bounds__(256, 2) rbf_fused(
    const float* __restrict__ x,         // [4096,16]
    const float* __restrict__ xx,        // [4096,16]
    const float* __restrict__ scale_ff,  // [16]
    const float* __restrict__ var_ff,    // scalar
    float* __restrict__ out)             // [4096,4096]
{
    __shared__ __align__(16) float Ud[16][256];  // dup pairs: Ud[d][2i]=Ud[d][2i+1]=u_i
    __shared__ __align__(16) float Vs[16][128];
    __shared__ float cs[128];
    __shared__ float dsm[128];
    __shared__ float s_inv[16];
    __shared__ float s_l2var;

    const int tid = threadIdx.x;
    const int tx = tid & 15;
    const int ty = tid >> 4;
    const int bi0 = blockIdx.y * 128;
    const int bj0 = blockIdx.x * 128;

    // ---- preamble: row LDG.128 x4 first, softplus overlapped (R7 scheme) ----
    const bool is_x = (tid < 128);
    const float4* rowp = is_x
        ? (const float4*)(x  + (size_t)(bi0 + tid) * 16)
        : (const float4*)(xx + (size_t)(bj0 + (tid - 128)) * 16);
    float4 ra = rowp[0], rb = rowp[1], rc = rowp[2], rd = rowp[3];

    if (tid < 16) {
        s_inv[tid] = 1.0f / log1pf(__expf(scale_ff[tid]));
    } else if (tid == 16) {
        s_l2var = log2f(log1pf(__expf(var_ff[0])));
    }
    __syncthreads();

    {
        float v[16] = {ra.x, ra.y, ra.z, ra.w, rb.x, rb.y, rb.z, rb.w,
                       rc.x, rc.y, rc.z, rc.w, rd.x, rd.y, rd.z, rd.w};
        float s2 = 0.0f;
        if (is_x) {
#pragma unroll
            for (int d = 0; d < 16; d++) {
                float u = v[d] * s_inv[d];
                ((float2*)&Ud[d][0])[tid] = make_float2(u, u);
                s2 = fmaf(u, u, s2);
            }
            cs[tid] = -0.5f * LOG2E * s2;
        } else {
            const int j = tid - 128;
#pragma unroll
            for (int d = 0; d < 16; d++) {
                float u = v[d] * s_inv[d];
                Vs[d][j] = LOG2E * u;
                s2 = fmaf(u, u, s2);
            }
            dsm[j] = -0.5f * LOG2E * s2 + s_l2var;
        }
    }
    __syncthreads();

    // per-thread row constants (8 i-rows)
    float cv[8];
#pragma unroll
    for (int r = 0; r < 4; r++) {
        cv[r]     = cs[ty * 4 + r];
        cv[4 + r] = cs[64 + ty * 4 + r];
    }

    // ---- two j-halves: jb=0 -> j in [4tx, 4tx+3], jb=1 -> +64 ----
#pragma unroll
    for (int jb = 0; jb < 2; jb++) {
        const int joff = jb * 64;

        // acc init: acc = c_i + d_j  (4 j per half -> 2 u64 per row)
        float2 dj0 = *(const float2*)&dsm[joff + 4 * tx];
        float2 dj1 = *(const float2*)&dsm[joff + 4 * tx + 2];
        unsigned long long acc[8][2];
#pragma unroll
        for (int ii = 0; ii < 8; ii++) {
            float l0 = cv[ii] + dj0.x, h0 = cv[ii] + dj0.y;
            float l1 = cv[ii] + dj1.x, h1 = cv[ii] + dj1.y;
            asm("mov.b64 %0, {%1, %2};" : "=l"(acc[ii][0]) : "f"(l0), "f"(h0));
            asm("mov.b64 %0, {%1, %2};" : "=l"(acc[ii][1]) : "f"(l1), "f"(h1));
        }

        // mainloop: D=16 unrolled; 4 u-LDS.128 + 1 v-LDS.128, 16 FMA2 per d
#pragma unroll
        for (int d = 0; d < 16; d++) {
            const ulonglong2* up = (const ulonglong2*)&Ud[d][0];
            ulonglong2 va = ((const ulonglong2*)&Vs[d][0])[jb * 16 + tx];
            ulonglong2 u0 = up[2 * ty];        // dup(i0),dup(i1)
            ulonglong2 u1 = up[2 * ty + 1];    // dup(i2),dup(i3)
            ulonglong2 u2 = up[32 + 2 * ty];   // dup(i4),dup(i5)
            ulonglong2 u3 = up[33 + 2 * ty];   // dup(i6),dup(i7)

            FMA2(acc[0][0], u0.x, va.x); FMA2(acc[0][1], u0.x, va.y);
            FMA2(acc[1][0], u0.y, va.x); FMA2(acc[1][1], u0.y, va.y);
            FMA2(acc[2][0], u1.x, va.x); FMA2(acc[2][1], u1.x, va.y);
            FMA2(acc[3][0], u1.y, va.x); FMA2(acc[3][1], u1.y, va.y);
            FMA2(acc[4][0], u2.x, va.x); FMA2(acc[4][1], u2.x, va.y);
            FMA2(acc[5][0], u2.y, va.x); FMA2(acc[5][1], u2.y, va.y);
            FMA2(acc[6][0], u3.x, va.x); FMA2(acc[6][1], u3.x, va.y);
            FMA2(acc[7][0], u3.y, va.x); FMA2(acc[7][1], u3.y, va.y);
        }

        // epilogue for this half: EX2 + one STG.128 per row
#pragma unroll
        for (int ii = 0; ii < 8; ii++) {
            int ig = bi0 + ((ii < 4) ? (ty * 4 + ii) : (64 + ty * 4 + (ii - 4)));
            float f0, f1, f2, f3;
            asm("mov.b64 {%0, %1}, %2;" : "=f"(f0), "=f"(f1) : "l"(acc[ii][0]));
            asm("mov.b64 {%0, %1}, %2;" : "=f"(f2), "=f"(f3) : "l"(acc[ii][1]));
            asm("ex2.approx.ftz.f32 %0, %0;" : "+f"(f0));
            asm("ex2.approx.ftz.f32 %0, %0;" : "+f"(f1));
            asm("ex2.approx.ftz.f32 %0, %0;" : "+f"(f2));
            asm("ex2.approx.ftz.f32 %0, %0;" : "+f"(f3));
            *(float4*)&out[(size_t)ig * NPTS + bj0 + joff + 4 * tx] =
                make_float4(f0, f1, f2, f3);
        }
    }
}

extern "C" void kernel_launch(void* const* d_in, const int* in_sizes, int n_in,
                              void* d_out, int out_size) {
    const float* x        = (const float*)d_in[0];
    const float* xx       = (const float*)d_in[1];
    const float* scale_ff = (const float*)d_in[2];
    const float* var_ff   = (const float*)d_in[3];
    float* out = (float*)d_out;

    dim3 grid(NPTS / 128, NPTS / 128);
    rbf_fused<<<grid, 256>>>(x, xx, scale_ff, var_ff, out);
}

// round 10
// speedup vs baseline: 1.7222x; 1.0986x over previous
#include <cuda_runtime.h>
#include <cuda_bf16.h>
#include <cstdint>

#define LOG2E 1.4426950408889634f
#define NPTS 4096

// mma.sync m16n8k16 bf16 (row.col), f32 accum — PTX-portable tensor path.
#define MMA16816(c, a, b)                                                      \
    asm("mma.sync.aligned.m16n8k16.row.col.f32.bf16.bf16.f32 "                 \
        "{%0,%1,%2,%3}, {%4,%5,%6,%7}, {%8,%9}, {%0,%1,%2,%3};"                \
        : "+f"((c)[0]), "+f"((c)[1]), "+f"((c)[2]), "+f"((c)[3])               \
        : "r"((a)[0]), "r"((a)[1]), "r"((a)[2]), "r"((a)[3]),                  \
          "r"((b)[0]), "r"((b)[1]))

__device__ __forceinline__ uint32_t pack_bf2(__nv_bfloat16 a, __nv_bfloat16 b) {
    __nv_bfloat162 t(a, b);
    return *reinterpret_cast<uint32_t*>(&t);
}

// cov[i,j] = exp2( S_ij + c_i + d_j ),  S = Uhat . (log2e * Vhat)^T
// 3-term bf16 split GEMM, K=48: A=[uh|ul|uh], B=[vh|vh|vl].
// 128x128 tile/CTA, 8 warps x (32x64), norm terms folded into C-frag init.
__global__ void __launch_bounds__(256, 2) rbf_mma(
    const float* __restrict__ x,         // [4096,16]
    const float* __restrict__ xx,        // [4096,16]
    const float* __restrict__ scale_ff,  // [16]
    const float* __restrict__ var_ff,    // scalar
    float* __restrict__ out)             // [4096,4096]
{
    __shared__ __align__(16) uint32_t Asm[128 * 28];  // 112B/row (K=56 pad)
    __shared__ __align__(16) uint32_t Bsm[128 * 28];
    __shared__ float CS[128];
    __shared__ float DS[128];
    __shared__ float SINV[17];

    const int tid  = threadIdx.x;
    const int wid  = tid >> 5;
    const int lane = tid & 31;
    const int bi0  = blockIdx.y * 128;
    const int bj0  = blockIdx.x * 128;

    // ---- preamble: row LDGs first; softplus on warp 1 overlapped ----
    const bool is_x = (tid < 128);
    const float4* rowp = is_x
        ? (const float4*)(x  + (size_t)(bi0 + tid) * 16)
        : (const float4*)(xx + (size_t)(bj0 + (tid - 128)) * 16);
    float4 ra = rowp[0], rb = rowp[1], rc = rowp[2], rd = rowp[3];

    if (tid >= 32 && tid < 48) {
        SINV[tid - 32] = 1.0f / log1pf(__expf(scale_ff[tid - 32]));
    } else if (tid == 48) {
        SINV[16] = log2f(log1pf(__expf(var_ff[0])));
    }
    __syncthreads();

    // ---- split rows into bf16 hi/lo, write K=48(+pad) layout ----
    {
        float vals[16] = {ra.x, ra.y, ra.z, ra.w, rb.x, rb.y, rb.z, rb.w,
                          rc.x, rc.y, rc.z, rc.w, rd.x, rd.y, rd.z, rd.w};
        const int row = tid & 127;
        uint32_t hp[8], lp[8];
        float s2 = 0.0f;
#pragma unroll
        for (int d = 0; d < 16; d += 2) {
            float u0 = vals[d] * SINV[d];
            float u1 = vals[d + 1] * SINV[d + 1];
            s2 = fmaf(u0, u0, fmaf(u1, u1, s2));
            float w0 = is_x ? u0 : (LOG2E * u0);
            float w1 = is_x ? u1 : (LOG2E * u1);
            __nv_bfloat16 h0 = __float2bfloat16_rn(w0);
            __nv_bfloat16 h1 = __float2bfloat16_rn(w1);
            __nv_bfloat16 l0 = __float2bfloat16_rn(w0 - __bfloat162float(h0));
            __nv_bfloat16 l1 = __float2bfloat16_rn(w1 - __bfloat162float(h1));
            hp[d >> 1] = pack_bf2(h0, h1);
            lp[d >> 1] = pack_bf2(l0, l1);
        }
        uint4 H0 = make_uint4(hp[0], hp[1], hp[2], hp[3]);
        uint4 H1 = make_uint4(hp[4], hp[5], hp[6], hp[7]);
        uint4 L0 = make_uint4(lp[0], lp[1], lp[2], lp[3]);
        uint4 L1 = make_uint4(lp[4], lp[5], lp[6], lp[7]);
        uint4 Z  = make_uint4(0, 0, 0, 0);
        if (is_x) {
            uint4* dst = (uint4*)(Asm + row * 28);
            dst[0] = H0; dst[1] = H1;   // k0: uh
            dst[2] = L0; dst[3] = L1;   // k1: ul
            dst[4] = H0; dst[5] = H1;   // k2: uh
            dst[6] = Z;
            CS[row] = -0.5f * LOG2E * s2;
        } else {
            uint4* dst = (uint4*)(Bsm + row * 28);
            dst[0] = H0; dst[1] = H1;   // k0: vh
            dst[2] = H0; dst[3] = H1;   // k1: vh
            dst[4] = L0; dst[5] = L1;   // k2: vl
            dst[6] = Z;
            DS[row] = -0.5f * LOG2E * s2 + SINV[16];
        }
    }
    __syncthreads();

    // ---- fragment indices ----
    const int qrow = lane >> 2;   // T/4 : row within m16 / n within n8
    const int qcol = lane & 3;    // T%4 : k-pair selector
    const int wr = (wid & 3) * 32;   // warp row base (i)
    const int wc = (wid >> 2) * 64;  // warp col base (j)

    // ---- acc init: C = c_i + d_j ----
    float ci[4];
#pragma unroll
    for (int t = 0; t < 4; t++) ci[t] = CS[wr + qrow + 8 * t];

    float acc[2][8][4];
#pragma unroll
    for (int nt = 0; nt < 8; nt++) {
        float2 dj = *(const float2*)&DS[wc + nt * 8 + 2 * qcol];
#pragma unroll
        for (int mt = 0; mt < 2; mt++) {
            acc[mt][nt][0] = ci[2 * mt] + dj.x;
            acc[mt][nt][1] = ci[2 * mt] + dj.y;
            acc[mt][nt][2] = ci[2 * mt + 1] + dj.x;
            acc[mt][nt][3] = ci[2 * mt + 1] + dj.y;
        }
    }

    // ---- K loop: 3 k16 steps, conflict-free direct LDS fragments ----
#pragma unroll
    for (int ks = 0; ks < 3; ks++) {
        const int kw = ks * 8 + qcol;   // word offset within row
        uint32_t a[2][4];
#pragma unroll
        for (int mt = 0; mt < 2; mt++) {
            const int r0 = wr + mt * 16 + qrow;
            a[mt][0] = Asm[r0 * 28 + kw];
            a[mt][1] = Asm[(r0 + 8) * 28 + kw];
            a[mt][2] = Asm[r0 * 28 + kw + 4];
            a[mt][3] = Asm[(r0 + 8) * 28 + kw + 4];
        }
        uint32_t b[8][2];
#pragma unroll
        for (int nt = 0; nt < 8; nt++) {
            const int jr = wc + nt * 8 + qrow;
            b[nt][0] = Bsm[jr * 28 + kw];
            b[nt][1] = Bsm[jr * 28 + kw + 4];
        }
#pragma unroll
        for (int mt = 0; mt < 2; mt++)
#pragma unroll
            for (int nt = 0; nt < 8; nt++)
                MMA16816(acc[mt][nt], a[mt], b[nt]);
    }

    // ---- epilogue: EX2 + STG.64 (32B-coalesced segments) ----
#pragma unroll
    for (int mt = 0; mt < 2; mt++) {
        const int r0 = bi0 + wr + mt * 16 + qrow;
#pragma unroll
        for (int nt = 0; nt < 8; nt++) {
            float f0 = acc[mt][nt][0], f1 = acc[mt][nt][1];
            float f2 = acc[mt][nt][2], f3 = acc[mt][nt][3];
            asm("ex2.approx.ftz.f32 %0, %0;" : "+f"(f0));
            asm("ex2.approx.ftz.f32 %0, %0;" : "+f"(f1));
            asm("ex2.approx.ftz.f32 %0, %0;" : "+f"(f2));
            asm("ex2.approx.ftz.f32 %0, %0;" : "+f"(f3));
            const int col = bj0 + wc + nt * 8 + 2 * qcol;
            *(float2*)&out[(size_t)r0 * NPTS + col]       = make_float2(f0, f1);
            *(float2*)&out[(size_t)(r0 + 8) * NPTS + col] = make_float2(f2, f3);
        }
    }
}

extern "C" void kernel_launch(void* const* d_in, const int* in_sizes, int n_in,
                              void* d_out, int out_size) {
    const float* x        = (const float*)d_in[0];
    const float* xx       = (const float*)d_in[1];
    const float* scale_ff = (const float*)d_in[2];
    const float* var_ff   = (const float*)d_in[3];
    float* out = (float*)d_out;

    dim3 grid(NPTS / 128, NPTS / 128);
    rbf_mma<<<grid, 256>>>(x, xx, scale_ff, var_ff, out);
}

// round 11
// speedup vs baseline: 1.8703x; 1.0860x over previous
#include <cuda_runtime.h>
#include <cuda_bf16.h>
#include <cstdint>

#define LOG2E 1.4426950408889634f
#define NPTS 4096
#define NT 1024                       // 32x32 tiles of 128x128

// mma.sync m16n8k16 bf16 (row.col), f32 accum — PTX-portable tensor path.
#define MMA16816(c, a, b)                                                      \
    asm("mma.sync.aligned.m16n8k16.row.col.f32.bf16.bf16.f32 "                 \
        "{%0,%1,%2,%3}, {%4,%5,%6,%7}, {%8,%9}, {%0,%1,%2,%3};"                \
        : "+f"((c)[0]), "+f"((c)[1]), "+f"((c)[2]), "+f"((c)[3])               \
        : "r"((a)[0]), "r"((a)[1]), "r"((a)[2]), "r"((a)[3]),                  \
          "r"((b)[0]), "r"((b)[1]))

// dynamic smem byte offsets: double-buffered A/B (112B rows), CS/DS, params
#define AOFF(b)  ((b) * 28672)
#define BOFF(b)  ((b) * 28672 + 14336)
#define CSOFF(b) (57344 + (b) * 1024)
#define DSOFF(b) (57344 + (b) * 1024 + 512)
#define PRMOFF   59392
#define SMEM_REQ 59520

extern __shared__ char smem[];

__device__ __forceinline__ uint32_t pack_bf2(__nv_bfloat16 a, __nv_bfloat16 b) {
    __nv_bfloat162 t(a, b);
    return *reinterpret_cast<uint32_t*>(&t);
}

// Persistent-CTA RBF: cov[i,j] = exp2( S_ij + c_i + d_j ),
// S = 3-term bf16 split GEMM (K=48: A=[uh|ul|uh], B=[vh|vh|vl]).
// Per tile: convert regs->smem[buf], prefetch next tile's rows (LDG in
// flight over MMA+epilogue), one sync, MMA + EX2 + STG. buf flips per tile.
__global__ void __launch_bounds__(256, 2) rbf_mma_p(
    const float* __restrict__ x,         // [4096,16]
    const float* __restrict__ xx,        // [4096,16]
    const float* __restrict__ scale_ff,  // [16]
    const float* __restrict__ var_ff,    // scalar
    float* __restrict__ out)             // [4096,4096]
{
    const int tid  = threadIdx.x;
    const int wid  = tid >> 5;
    const int lane = tid & 31;
    float* SINV = (float*)(smem + PRMOFF);   // [16] inv-scale, [16]=log2(var)

    // softplus params on warp 1 (overlaps first-tile LDGs below)
    if (tid >= 32 && tid < 48) {
        SINV[tid - 32] = 1.0f / log1pf(__expf(scale_ff[tid - 32]));
    } else if (tid == 48) {
        SINV[16] = log2f(log1pf(__expf(var_ff[0])));
    }

    const bool is_x = (tid < 128);
    const int rowid = tid & 127;

    int t = blockIdx.x;
    float4 ra, rb, rc, rd;
    if (t < NT) {
        const int bi0 = (t >> 5) * 128, bj0 = (t & 31) * 128;
        const float4* rowp = is_x
            ? (const float4*)(x  + (size_t)(bi0 + rowid) * 16)
            : (const float4*)(xx + (size_t)(bj0 + rowid) * 16);
        ra = rowp[0]; rb = rowp[1]; rc = rowp[2]; rd = rowp[3];
    }
    __syncthreads();   // SINV ready

    const int qrow = lane >> 2;
    const int qcol = lane & 3;
    const int wr = (wid & 3) * 32;
    const int wc = (wid >> 2) * 64;

    int buf = 0;
    while (t < NT) {
        const int bi0 = (t >> 5) * 128, bj0 = (t & 31) * 128;
        const int tn = t + gridDim.x;

        // ---- convert current rows -> smem[buf] ----
        {
            float vals[16] = {ra.x, ra.y, ra.z, ra.w, rb.x, rb.y, rb.z, rb.w,
                              rc.x, rc.y, rc.z, rc.w, rd.x, rd.y, rd.z, rd.w};
            uint32_t hp[8], lp[8];
            float s2 = 0.0f;
#pragma unroll
            for (int d = 0; d < 16; d += 2) {
                float u0 = vals[d] * SINV[d];
                float u1 = vals[d + 1] * SINV[d + 1];
                s2 = fmaf(u0, u0, fmaf(u1, u1, s2));
                float w0 = is_x ? u0 : (LOG2E * u0);
                float w1 = is_x ? u1 : (LOG2E * u1);
                __nv_bfloat16 h0 = __float2bfloat16_rn(w0);
                __nv_bfloat16 h1 = __float2bfloat16_rn(w1);
                __nv_bfloat16 l0 = __float2bfloat16_rn(w0 - __bfloat162float(h0));
                __nv_bfloat16 l1 = __float2bfloat16_rn(w1 - __bfloat162float(h1));
                hp[d >> 1] = pack_bf2(h0, h1);
                lp[d >> 1] = pack_bf2(l0, l1);
            }
            uint4 H0 = make_uint4(hp[0], hp[1], hp[2], hp[3]);
            uint4 H1 = make_uint4(hp[4], hp[5], hp[6], hp[7]);
            uint4 L0 = make_uint4(lp[0], lp[1], lp[2], lp[3]);
            uint4 L1 = make_uint4(lp[4], lp[5], lp[6], lp[7]);
            if (is_x) {
                uint4* dst = (uint4*)(smem + AOFF(buf) + rowid * 112);
                dst[0] = H0; dst[1] = H1;   // k0: uh
                dst[2] = L0; dst[3] = L1;   // k1: ul
                dst[4] = H0; dst[5] = H1;   // k2: uh
                ((float*)(smem + CSOFF(buf)))[rowid] = -0.5f * LOG2E * s2;
            } else {
                uint4* dst = (uint4*)(smem + BOFF(buf) + rowid * 112);
                dst[0] = H0; dst[1] = H1;   // k0: vh
                dst[2] = H0; dst[3] = H1;   // k1: vh
                dst[4] = L0; dst[5] = L1;   // k2: vl
                ((float*)(smem + DSOFF(buf)))[rowid] =
                    -0.5f * LOG2E * s2 + SINV[16];
            }
        }

        // ---- prefetch next tile's rows (in flight over MMA+epilogue) ----
        if (tn < NT) {
            const int nbi = (tn >> 5) * 128, nbj = (tn & 31) * 128;
            const float4* rowp = is_x
                ? (const float4*)(x  + (size_t)(nbi + rowid) * 16)
                : (const float4*)(xx + (size_t)(nbj + rowid) * 16);
            ra = rowp[0]; rb = rowp[1]; rc = rowp[2]; rd = rowp[3];
        }
        __syncthreads();   // smem[buf] ready (also fences buf reuse, see note)

        // ---- compute tile t from smem[buf] ----
        const uint32_t* A   = (const uint32_t*)(smem + AOFF(buf));
        const uint32_t* B   = (const uint32_t*)(smem + BOFF(buf));
        const float*    CSb = (const float*)(smem + CSOFF(buf));
        const float*    DSb = (const float*)(smem + DSOFF(buf));

        float ci[4];
#pragma unroll
        for (int q = 0; q < 4; q++) ci[q] = CSb[wr + qrow + 8 * q];

        float acc[2][8][4];
#pragma unroll
        for (int nt = 0; nt < 8; nt++) {
            float2 dj = *(const float2*)&DSb[wc + nt * 8 + 2 * qcol];
#pragma unroll
            for (int mt = 0; mt < 2; mt++) {
                acc[mt][nt][0] = ci[2 * mt] + dj.x;
                acc[mt][nt][1] = ci[2 * mt] + dj.y;
                acc[mt][nt][2] = ci[2 * mt + 1] + dj.x;
                acc[mt][nt][3] = ci[2 * mt + 1] + dj.y;
            }
        }

#pragma unroll
        for (int ks = 0; ks < 3; ks++) {
            const int kw = ks * 8 + qcol;
            uint32_t a[2][4];
#pragma unroll
            for (int mt = 0; mt < 2; mt++) {
                const int r0 = wr + mt * 16 + qrow;
                a[mt][0] = A[r0 * 28 + kw];
                a[mt][1] = A[(r0 + 8) * 28 + kw];
                a[mt][2] = A[r0 * 28 + kw + 4];
                a[mt][3] = A[(r0 + 8) * 28 + kw + 4];
            }
            uint32_t b[8][2];
#pragma unroll
            for (int nt = 0; nt < 8; nt++) {
                const int jr = wc + nt * 8 + qrow;
                b[nt][0] = B[jr * 28 + kw];
                b[nt][1] = B[jr * 28 + kw + 4];
            }
#pragma unroll
            for (int mt = 0; mt < 2; mt++)
#pragma unroll
                for (int nt = 0; nt < 8; nt++)
                    MMA16816(acc[mt][nt], a[mt], b[nt]);
        }

        // ---- epilogue: EX2 + STG.64 ----
#pragma unroll
        for (int mt = 0; mt < 2; mt++) {
            const int r0 = bi0 + wr + mt * 16 + qrow;
#pragma unroll
            for (int nt = 0; nt < 8; nt++) {
                float f0 = acc[mt][nt][0], f1 = acc[mt][nt][1];
                float f2 = acc[mt][nt][2], f3 = acc[mt][nt][3];
                asm("ex2.approx.ftz.f32 %0, %0;" : "+f"(f0));
                asm("ex2.approx.ftz.f32 %0, %0;" : "+f"(f1));
                asm("ex2.approx.ftz.f32 %0, %0;" : "+f"(f2));
                asm("ex2.approx.ftz.f32 %0, %0;" : "+f"(f3));
                const int col = bj0 + wc + nt * 8 + 2 * qcol;
                *(float2*)&out[(size_t)r0 * NPTS + col] = make_float2(f0, f1);
                *(float2*)&out[(size_t)(r0 + 8) * NPTS + col] =
                    make_float2(f2, f3);
            }
        }

        t = tn;
        buf ^= 1;
    }
}

extern "C" void kernel_launch(void* const* d_in, const int* in_sizes, int n_in,
                              void* d_out, int out_size) {
    const float* x        = (const float*)d_in[0];
    const float* xx       = (const float*)d_in[1];
    const float* scale_ff = (const float*)d_in[2];
    const float* var_ff   = (const float*)d_in[3];
    float* out = (float*)d_out;

    int sms = 148;
    cudaDeviceGetAttribute(&sms, cudaDevAttrMultiProcessorCount, 0);
    int grid = 2 * sms;
    if (grid > NT) grid = NT;

    cudaFuncSetAttribute(rbf_mma_p, cudaFuncAttributeMaxDynamicSharedMemorySize,
                         SMEM_REQ);
    rbf_mma_p<<<grid, 256, SMEM_REQ>>>(x, xx, scale_ff, var_ff, out);
}